// round 1
// baseline (speedup 1.0000x reference)
#include <cuda_runtime.h>

// Problem constants (fixed shapes for PQHotShared)
#define K_HOT   16384
#define R_DIM   64
#define D_DIM   4096
#define K_CB    2048
#define D_SUB   16
#define CB_CHUNK 512

// Scratch (device globals — no allocation allowed)
__device__ float g_Uq[K_HOT * R_DIM];
__device__ float g_Bq[R_DIM * D_DIM];

// ---------------------------------------------------------------------------
// PQ quantize: for each 16-wide subvector of W/rs, argmax over codewords of
// (g . cb - 0.5*||cb||^2)  ==  argmin of (||cb||^2 - 2 g.cb)  (reference d2).
// One thread per subvector; codebook streamed through SMEM in 512-cw chunks.
// ---------------------------------------------------------------------------
__global__ __launch_bounds__(256) void pq_quantize_kernel(
    const float* __restrict__ W, const float* __restrict__ rs,
    const float* __restrict__ cb, float* __restrict__ Wq,
    int nsub, int subs_per_row)
{
    __shared__ float cb_sh[CB_CHUNK * D_SUB];   // 32 KB
    __shared__ float hn_sh[CB_CHUNK];           // 2 KB

    const int tid = threadIdx.x;
    const int sv  = blockIdx.x * 256 + tid;
    const int rowlen = subs_per_row * D_SUB;

    float g[D_SUB];
    #pragma unroll
    for (int d = 0; d < D_SUB; ++d) g[d] = 0.f;

    int row = 0, off = 0;
    float rscale = 1.f;
    const bool valid = (sv < nsub);
    if (valid) {
        row = sv / subs_per_row;
        off = (sv - row * subs_per_row) * D_SUB;
        rscale = rs[row];
        const float4* wp = (const float4*)(W + row * rowlen + off);
        #pragma unroll
        for (int q = 0; q < 4; ++q) {
            float4 w = wp[q];
            g[4*q+0] = w.x / rscale;
            g[4*q+1] = w.y / rscale;
            g[4*q+2] = w.z / rscale;
            g[4*q+3] = w.w / rscale;
        }
    }

    float best = -3.402823466e+38f;
    int bidx = 0;

    for (int ch = 0; ch < K_CB; ch += CB_CHUNK) {
        __syncthreads();  // protect cb_sh readers from previous chunk
        // cooperative chunk load (float4, fully coalesced)
        {
            const float4* src = (const float4*)(cb + ch * D_SUB);
            float4* dst = (float4*)cb_sh;
            for (int i = tid; i < CB_CHUNK * D_SUB / 4; i += 256)
                dst[i] = src[i];
        }
        __syncthreads();
        // half-norms
        for (int c = tid; c < CB_CHUNK; c += 256) {
            float s = 0.f;
            #pragma unroll
            for (int d = 0; d < D_SUB; ++d) {
                float v = cb_sh[c * D_SUB + d];
                s = fmaf(v, v, s);
            }
            hn_sh[c] = 0.5f * s;
        }
        __syncthreads();
        // scan chunk: all threads walk codewords in lockstep (broadcast LDS)
        #pragma unroll 4
        for (int c = 0; c < CB_CHUNK; ++c) {
            const float4* crow = (const float4*)(cb_sh + c * D_SUB);
            float dot = 0.f;
            #pragma unroll
            for (int q = 0; q < 4; ++q) {
                float4 w = crow[q];
                dot = fmaf(g[4*q+0], w.x, dot);
                dot = fmaf(g[4*q+1], w.y, dot);
                dot = fmaf(g[4*q+2], w.z, dot);
                dot = fmaf(g[4*q+3], w.w, dot);
            }
            float sc = dot - hn_sh[c];
            if (sc > best) { best = sc; bidx = ch + c; }   // strict > keeps first max (argmin tie rule)
        }
    }

    if (valid) {
        const float4* srcw = (const float4*)(cb + bidx * D_SUB);
        float4* dq = (float4*)(Wq + row * rowlen + off);
        #pragma unroll
        for (int q = 0; q < 4; ++q) {
            float4 v = srcw[q];
            v.x *= rscale; v.y *= rscale; v.z *= rscale; v.w *= rscale;
            dq[q] = v;
        }
    }
}

// ---------------------------------------------------------------------------
// fp32 GEMM: C[16384,4096] = A[16384,64] @ B[64,4096].
// K=64 fits in a single SMEM stage. 128x128 block tile, 8x8 register tile,
// A stored k-major with +4 padding (conflict-free float4 reads).
// ---------------------------------------------------------------------------
#define AS_LD 132
#define BS_LD 128
#define GEMM_SMEM ((R_DIM * AS_LD + R_DIM * BS_LD) * 4)

__global__ __launch_bounds__(256) void lr_gemm_kernel(
    const float* __restrict__ A, const float* __restrict__ B,
    float* __restrict__ C)
{
    extern __shared__ float sm[];
    float* As = sm;                    // [64][132] k-major
    float* Bs = sm + R_DIM * AS_LD;    // [64][128]

    const int tid = threadIdx.x;
    const int tx = tid & 15;
    const int ty = tid >> 4;
    const int row0 = blockIdx.y * 128;
    const int col0 = blockIdx.x * 128;

    // A tile is a contiguous 128x64 block of memory (row-major, K==stride).
    {
        const float* Ab = A + row0 * R_DIM;
        for (int i = tid; i < 128 * R_DIM; i += 256) {
            int m = i >> 6, k = i & 63;
            As[k * AS_LD + m] = Ab[i];
        }
        const float* Bb = B + col0;
        for (int i = tid; i < R_DIM * 32; i += 256) {
            int k = i >> 5, c4 = i & 31;
            *(float4*)&Bs[k * BS_LD + c4 * 4] =
                *(const float4*)(Bb + k * D_DIM + c4 * 4);
        }
    }
    __syncthreads();

    float acc[8][8];
    #pragma unroll
    for (int i = 0; i < 8; ++i)
        #pragma unroll
        for (int j = 0; j < 8; ++j)
            acc[i][j] = 0.f;

    #pragma unroll 8
    for (int k = 0; k < R_DIM; ++k) {
        float a[8], b[8];
        *(float4*)(a)     = *(const float4*)&As[k * AS_LD + ty * 4];
        *(float4*)(a + 4) = *(const float4*)&As[k * AS_LD + 64 + ty * 4];
        *(float4*)(b)     = *(const float4*)&Bs[k * BS_LD + tx * 4];
        *(float4*)(b + 4) = *(const float4*)&Bs[k * BS_LD + 64 + tx * 4];
        #pragma unroll
        for (int i = 0; i < 8; ++i)
            #pragma unroll
            for (int j = 0; j < 8; ++j)
                acc[i][j] = fmaf(a[i], b[j], acc[i][j]);
    }

    #pragma unroll
    for (int i = 0; i < 8; ++i) {
        int r = row0 + ((i < 4) ? (ty * 4 + i) : (64 + ty * 4 + (i - 4)));
        float* Cr = C + (size_t)r * D_DIM + col0;
        *(float4*)(Cr + tx * 4) =
            make_float4(acc[i][0], acc[i][1], acc[i][2], acc[i][3]);
        *(float4*)(Cr + 64 + tx * 4) =
            make_float4(acc[i][4], acc[i][5], acc[i][6], acc[i][7]);
    }
}

// ---------------------------------------------------------------------------
extern "C" void kernel_launch(void* const* d_in, const int* in_sizes, int n_in,
                              void* d_out, int out_size)
{
    (void)in_sizes; (void)n_in; (void)out_size;
    const float* U   = (const float*)d_in[0];
    const float* B   = (const float*)d_in[1];
    const float* rsU = (const float*)d_in[2];
    const float* rsB = (const float*)d_in[3];
    const float* cb  = (const float*)d_in[4];
    float* out = (float*)d_out;

    float *uq = nullptr, *bq = nullptr;
    cudaGetSymbolAddress((void**)&uq, g_Uq);
    cudaGetSymbolAddress((void**)&bq, g_Bq);

    const int nsub_u = K_HOT * R_DIM / D_SUB;   // 65536
    const int nsub_b = R_DIM * D_DIM / D_SUB;   // 16384

    pq_quantize_kernel<<<(nsub_u + 255) / 256, 256>>>(
        U, rsU, cb, uq, nsub_u, R_DIM / D_SUB);
    pq_quantize_kernel<<<(nsub_b + 255) / 256, 256>>>(
        B, rsB, cb, bq, nsub_b, D_DIM / D_SUB);

    cudaFuncSetAttribute(lr_gemm_kernel,
                         cudaFuncAttributeMaxDynamicSharedMemorySize, GEMM_SMEM);
    dim3 grid(D_DIM / 128, K_HOT / 128);
    lr_gemm_kernel<<<grid, 256, GEMM_SMEM>>>(uq, bq, out);
}

// round 3
// speedup vs baseline: 1.2774x; 1.2774x over previous
#include <cuda_runtime.h>
#include <cuda_bf16.h>
#include <cstdint>

// Problem constants (fixed shapes for PQHotShared)
#define K_HOT   16384
#define R_DIM   64
#define D_DIM   4096
#define K_CB    2048
#define D_SUB   16
#define CB_CHUNK 512

// Scratch (device globals — no allocation allowed)
// Split-bf16 GEMM operands: A = Uq (K-major rows), Bt = Bq^T (K-major rows)
__device__ __nv_bfloat16 g_Ah[K_HOT * R_DIM];
__device__ __nv_bfloat16 g_Al[K_HOT * R_DIM];
__device__ __nv_bfloat16 g_Bh[D_DIM * R_DIM];   // transposed: [n][k]
__device__ __nv_bfloat16 g_Bl[D_DIM * R_DIM];

#define SW128(b) ((b) ^ (((b) >> 3) & 0x70))

__device__ __forceinline__ uint32_t smem_u32(const void* p) {
    uint32_t a;
    asm("{ .reg .u64 t; cvta.to.shared.u64 t, %1; cvt.u32.u64 %0, t; }"
        : "=r"(a) : "l"(p));
    return a;
}

__device__ __forceinline__ void ldmatrix_x4(uint32_t* r, uint32_t addr) {
    asm volatile("ldmatrix.sync.aligned.m8n8.x4.shared.b16 {%0,%1,%2,%3}, [%4];"
                 : "=r"(r[0]), "=r"(r[1]), "=r"(r[2]), "=r"(r[3]) : "r"(addr));
}

__device__ __forceinline__ void mma_bf16(float* c, const uint32_t* a,
                                         const uint32_t* b) {
    asm volatile(
        "mma.sync.aligned.m16n8k16.row.col.f32.bf16.bf16.f32 "
        "{%0,%1,%2,%3}, {%4,%5,%6,%7}, {%8,%9}, {%0,%1,%2,%3};"
        : "+f"(c[0]), "+f"(c[1]), "+f"(c[2]), "+f"(c[3])
        : "r"(a[0]), "r"(a[1]), "r"(a[2]), "r"(a[3]), "r"(b[0]), "r"(b[1]));
}

// ---------------------------------------------------------------------------
// PQ quantize (fp32 argmin identical to round-1 passing kernel) with
// split-bf16 output. transpose_out=1 writes W^T (for B).
// ---------------------------------------------------------------------------
__global__ __launch_bounds__(256) void pq_quantize_kernel(
    const float* __restrict__ W, const float* __restrict__ rs,
    const float* __restrict__ cb,
    __nv_bfloat16* __restrict__ Wh, __nv_bfloat16* __restrict__ Wl,
    int nsub, int subs_per_row, int transpose_out)
{
    __shared__ float cb_sh[CB_CHUNK * D_SUB];   // 32 KB
    __shared__ float hn_sh[CB_CHUNK];           // 2 KB

    const int tid = threadIdx.x;
    const int sv  = blockIdx.x * 256 + tid;
    const int rowlen = subs_per_row * D_SUB;

    float g[D_SUB];
    #pragma unroll
    for (int d = 0; d < D_SUB; ++d) g[d] = 0.f;

    int row = 0, off = 0;
    float rscale = 1.f;
    const bool valid = (sv < nsub);
    if (valid) {
        row = sv / subs_per_row;
        off = (sv - row * subs_per_row) * D_SUB;
        rscale = rs[row];
        const float4* wp = (const float4*)(W + row * rowlen + off);
        #pragma unroll
        for (int q = 0; q < 4; ++q) {
            float4 w = wp[q];
            g[4*q+0] = w.x / rscale;
            g[4*q+1] = w.y / rscale;
            g[4*q+2] = w.z / rscale;
            g[4*q+3] = w.w / rscale;
        }
    }

    float best = -3.402823466e+38f;
    int bidx = 0;

    for (int ch = 0; ch < K_CB; ch += CB_CHUNK) {
        __syncthreads();
        {
            const float4* src = (const float4*)(cb + ch * D_SUB);
            float4* dst = (float4*)cb_sh;
            for (int i = tid; i < CB_CHUNK * D_SUB / 4; i += 256)
                dst[i] = src[i];
        }
        __syncthreads();
        for (int c = tid; c < CB_CHUNK; c += 256) {
            float s = 0.f;
            #pragma unroll
            for (int d = 0; d < D_SUB; ++d) {
                float v = cb_sh[c * D_SUB + d];
                s = fmaf(v, v, s);
            }
            hn_sh[c] = 0.5f * s;
        }
        __syncthreads();
        #pragma unroll 4
        for (int c = 0; c < CB_CHUNK; ++c) {
            const float4* crow = (const float4*)(cb_sh + c * D_SUB);
            float dot = 0.f;
            #pragma unroll
            for (int q = 0; q < 4; ++q) {
                float4 w = crow[q];
                dot = fmaf(g[4*q+0], w.x, dot);
                dot = fmaf(g[4*q+1], w.y, dot);
                dot = fmaf(g[4*q+2], w.z, dot);
                dot = fmaf(g[4*q+3], w.w, dot);
            }
            float sc = dot - hn_sh[c];
            if (sc > best) { best = sc; bidx = ch + c; }   // strict > == argmin first-min
        }
    }

    if (valid) {
        const float* srcw = cb + bidx * D_SUB;
        if (!transpose_out) {
            __nv_bfloat16* dh = Wh + row * rowlen + off;
            __nv_bfloat16* dl = Wl + row * rowlen + off;
            #pragma unroll
            for (int j = 0; j < D_SUB; ++j) {
                float v = srcw[j] * rscale;
                __nv_bfloat16 h = __float2bfloat16(v);
                dh[j] = h;
                dl[j] = __float2bfloat16(v - __bfloat162float(h));
            }
        } else {
            #pragma unroll
            for (int j = 0; j < D_SUB; ++j) {
                float v = srcw[j] * rscale;
                __nv_bfloat16 h = __float2bfloat16(v);
                Wh[(off + j) * R_DIM + row] = h;
                Wl[(off + j) * R_DIM + row] =
                    __float2bfloat16(v - __bfloat162float(h));
            }
        }
    }
}

// ---------------------------------------------------------------------------
// Split-bf16 GEMM on mma.sync: C[16384,4096] = (Ah+Al) @ (Bh+Bl)^T.
// A, Bt K-major (64 bf16 = 128 B rows), SW128-swizzled in SMEM for
// conflict-free ldmatrix. 128x128 block, 8 warps (4x2), 32x64 per warp.
// ---------------------------------------------------------------------------
#define OFF_AH 0
#define OFF_AL 16384
#define OFF_BH 32768
#define OFF_BL 49152
#define GEMM_SMEM (4 * 16384)

__device__ __forceinline__ void load_tile_128x64(
    char* smem, int off, const __nv_bfloat16* __restrict__ src, int tid)
{
    // 128 rows x 128 bytes, SW128 swizzle; 16B chunks, 256 threads, 4 iters
    #pragma unroll
    for (int it = 0; it < 4; ++it) {
        int i = tid + it * 256;
        int m = i >> 3, q = i & 7;
        uint32_t b = (uint32_t)(m * 128 + q * 16);
        *(uint4*)(smem + off + SW128(b)) = ((const uint4*)(src + m * 64))[q];
    }
}

__global__ __launch_bounds__(256) void mma_gemm_kernel(
    const __nv_bfloat16* __restrict__ Ah, const __nv_bfloat16* __restrict__ Al,
    const __nv_bfloat16* __restrict__ Bh, const __nv_bfloat16* __restrict__ Bl,
    float* __restrict__ C)
{
    extern __shared__ char smem[];
    const uint32_t sbase = smem_u32(smem);
    const int tid = threadIdx.x;
    const int wid = tid >> 5, lane = tid & 31;
    const int row0 = blockIdx.y * 128;
    const int col0 = blockIdx.x * 128;

    load_tile_128x64(smem, OFF_AH, Ah + (size_t)row0 * R_DIM, tid);
    load_tile_128x64(smem, OFF_AL, Al + (size_t)row0 * R_DIM, tid);
    load_tile_128x64(smem, OFF_BH, Bh + (size_t)col0 * R_DIM, tid);
    load_tile_128x64(smem, OFF_BL, Bl + (size_t)col0 * R_DIM, tid);
    __syncthreads();

    const int warp_m = wid & 3;          // 4 row groups of 32
    const int warp_n = wid >> 2;         // 2 col groups of 64
    const int mbase = warp_m * 32;
    const int nbase = warp_n * 64;

    // ldmatrix lane->row/koffset mappings (logical, pre-swizzle)
    const int a_row = mbase + (lane & 15);          // + mt*16
    const int a_kb  = (lane >> 4) * 16;             // + k*32
    const int b_nrow = nbase + (lane & 7) + (lane >> 4) * 8;  // + nt*8
    const int b_kb   = ((lane >> 3) & 1) * 16;      // + k*32

    float acc[2][8][4];
    #pragma unroll
    for (int mt = 0; mt < 2; ++mt)
        #pragma unroll
        for (int nt = 0; nt < 8; ++nt)
            #pragma unroll
            for (int q = 0; q < 4; ++q) acc[mt][nt][q] = 0.f;

    // 3 passes: Ah*Bh, Ah*Bl, Al*Bh
    #pragma unroll
    for (int pass = 0; pass < 3; ++pass) {
        const uint32_t abase = sbase + (pass == 2 ? OFF_AL : OFF_AH);
        const uint32_t bbase = sbase + (pass == 1 ? OFF_BL : OFF_BH);
        #pragma unroll
        for (int k = 0; k < 4; ++k) {
            uint32_t a[2][4];
            #pragma unroll
            for (int mt = 0; mt < 2; ++mt) {
                uint32_t b = (uint32_t)((a_row + mt * 16) * 128 + k * 32 + a_kb);
                ldmatrix_x4(a[mt], abase + SW128(b));
            }
            uint32_t bf[8][2];
            #pragma unroll
            for (int np = 0; np < 4; ++np) {   // two n-tiles per x4
                uint32_t b = (uint32_t)((b_nrow + np * 16) * 128 + k * 32 + b_kb);
                uint32_t r[4];
                ldmatrix_x4(r, bbase + SW128(b));
                bf[np * 2][0] = r[0]; bf[np * 2][1] = r[1];
                bf[np * 2 + 1][0] = r[2]; bf[np * 2 + 1][1] = r[3];
            }
            #pragma unroll
            for (int mt = 0; mt < 2; ++mt)
                #pragma unroll
                for (int nt = 0; nt < 8; ++nt)
                    mma_bf16(acc[mt][nt], a[mt], bf[nt]);
        }
    }

    // Epilogue: fragment rows g=lane>>2 (+8), cols 2*(lane&3) within n8 tile.
    const int g = lane >> 2, t = lane & 3;
    #pragma unroll
    for (int mt = 0; mt < 2; ++mt) {
        float* Cr0 = C + (size_t)(row0 + mbase + mt * 16 + g) * D_DIM + col0 + nbase;
        float* Cr1 = Cr0 + 8 * D_DIM;
        #pragma unroll
        for (int nt = 0; nt < 8; ++nt) {
            *(float2*)(Cr0 + nt * 8 + t * 2) =
                make_float2(acc[mt][nt][0], acc[mt][nt][1]);
            *(float2*)(Cr1 + nt * 8 + t * 2) =
                make_float2(acc[mt][nt][2], acc[mt][nt][3]);
        }
    }
}

// ---------------------------------------------------------------------------
extern "C" void kernel_launch(void* const* d_in, const int* in_sizes, int n_in,
                              void* d_out, int out_size)
{
    (void)in_sizes; (void)n_in; (void)out_size;
    const float* U   = (const float*)d_in[0];
    const float* B   = (const float*)d_in[1];
    const float* rsU = (const float*)d_in[2];
    const float* rsB = (const float*)d_in[3];
    const float* cb  = (const float*)d_in[4];
    float* out = (float*)d_out;

    __nv_bfloat16 *ah, *al, *bh, *bl;
    cudaGetSymbolAddress((void**)&ah, g_Ah);
    cudaGetSymbolAddress((void**)&al, g_Al);
    cudaGetSymbolAddress((void**)&bh, g_Bh);
    cudaGetSymbolAddress((void**)&bl, g_Bl);

    const int nsub_u = K_HOT * R_DIM / D_SUB;   // 65536
    const int nsub_b = R_DIM * D_DIM / D_SUB;   // 16384

    pq_quantize_kernel<<<(nsub_u + 255) / 256, 256>>>(
        U, rsU, cb, ah, al, nsub_u, R_DIM / D_SUB, 0);
    pq_quantize_kernel<<<(nsub_b + 255) / 256, 256>>>(
        B, rsB, cb, bh, bl, nsub_b, D_DIM / D_SUB, 1);

    cudaFuncSetAttribute(mma_gemm_kernel,
                         cudaFuncAttributeMaxDynamicSharedMemorySize, GEMM_SMEM);
    dim3 grid(D_DIM / 128, K_HOT / 128);
    mma_gemm_kernel<<<grid, 256, GEMM_SMEM>>>(ah, al, bh, bl, out);
}

// round 5
// speedup vs baseline: 2.0241x; 1.5845x over previous
#include <cuda_runtime.h>
#include <cuda_bf16.h>
#include <cstdint>
#include <cfloat>

// Problem constants (fixed shapes for PQHotShared)
#define K_HOT   16384
#define R_DIM   64
#define D_DIM   4096
#define K_CB    2048
#define D_SUB   16

// Scratch (device globals — no allocation allowed)
__device__ __nv_bfloat16 g_Ah[K_HOT * R_DIM];
__device__ __nv_bfloat16 g_Al[K_HOT * R_DIM];
__device__ __nv_bfloat16 g_Bh[D_DIM * R_DIM];   // transposed: [n][k]
__device__ __nv_bfloat16 g_Bl[D_DIM * R_DIM];
__device__ uint32_t g_cbsplit[K_CB * 32];       // per cw: [2k]=tf32 hi, [2k+1]=tf32 lo
__device__ float    g_hn[K_CB];                 // 0.5*||cb||^2

#define SW128(b) ((b) ^ (((b) >> 3) & 0x70))

__device__ __forceinline__ uint32_t smem_u32(const void* p) {
    uint32_t a;
    asm("{ .reg .u64 t; cvta.to.shared.u64 t, %1; cvt.u32.u64 %0, t; }"
        : "=r"(a) : "l"(p));
    return a;
}

__device__ __forceinline__ void ldmatrix_x4(uint32_t* r, uint32_t addr) {
    asm volatile("ldmatrix.sync.aligned.m8n8.x4.shared.b16 {%0,%1,%2,%3}, [%4];"
                 : "=r"(r[0]), "=r"(r[1]), "=r"(r[2]), "=r"(r[3]) : "r"(addr));
}

__device__ __forceinline__ void mma_bf16(float* c, const uint32_t* a,
                                         const uint32_t* b) {
    asm volatile(
        "mma.sync.aligned.m16n8k16.row.col.f32.bf16.bf16.f32 "
        "{%0,%1,%2,%3}, {%4,%5,%6,%7}, {%8,%9}, {%0,%1,%2,%3};"
        : "+f"(c[0]), "+f"(c[1]), "+f"(c[2]), "+f"(c[3])
        : "r"(a[0]), "r"(a[1]), "r"(a[2]), "r"(a[3]), "r"(b[0]), "r"(b[1]));
}

__device__ __forceinline__ void mma_tf32(float* c, const uint32_t* a,
                                         const uint32_t* b) {
    asm volatile(
        "mma.sync.aligned.m16n8k8.row.col.f32.tf32.tf32.f32 "
        "{%0,%1,%2,%3}, {%4,%5,%6,%7}, {%8,%9}, {%0,%1,%2,%3};"
        : "+f"(c[0]), "+f"(c[1]), "+f"(c[2]), "+f"(c[3])
        : "r"(a[0]), "r"(a[1]), "r"(a[2]), "r"(a[3]), "r"(b[0]), "r"(b[1]));
}

__device__ __forceinline__ void split_tf32(float v, uint32_t& hi, uint32_t& lo) {
    uint32_t h;
    asm("cvt.rna.tf32.f32 %0, %1;" : "=r"(h) : "f"(v));
    float l = v - __uint_as_float(h);
    uint32_t lw;
    asm("cvt.rna.tf32.f32 %0, %1;" : "=r"(lw) : "f"(l));
    hi = h; lo = lw;
}

// ---------------------------------------------------------------------------
// Codebook prep: tf32 hi/lo split (interleaved) + half squared norms.
// ---------------------------------------------------------------------------
__global__ __launch_bounds__(256) void cb_prep_kernel(const float* __restrict__ cb)
{
    int cw = blockIdx.x * 256 + threadIdx.x;
    if (cw >= K_CB) return;
    float hn = 0.f;
    uint32_t out[32];
    #pragma unroll
    for (int j = 0; j < D_SUB; ++j) {
        float v = cb[cw * D_SUB + j];
        hn = fmaf(v, v, hn);
        split_tf32(v, out[2 * j], out[2 * j + 1]);
    }
    g_hn[cw] = 0.5f * hn;
    uint4* dst = (uint4*)&g_cbsplit[cw * 32];
    #pragma unroll
    for (int q = 0; q < 8; ++q)
        dst[q] = make_uint4(out[4 * q], out[4 * q + 1], out[4 * q + 2], out[4 * q + 3]);
}

// ---------------------------------------------------------------------------
// Fused PQ argmin via split-tf32 mma + dequant to split-bf16 GEMM operands.
// Block = 256 subvector rows (8 warps x 2 m16-tiles). Blocks [0,256): U rows,
// [256,320): B rows (written transposed).
// ---------------------------------------------------------------------------
#define QROWS 256
#define QCH   256
#define QSTRIDE 40

__global__ __launch_bounds__(256) void pq_argmin_kernel(
    const float* __restrict__ U, const float* __restrict__ B,
    const float* __restrict__ rsU, const float* __restrict__ rsB,
    const float* __restrict__ cb,
    __nv_bfloat16* __restrict__ Ah, __nv_bfloat16* __restrict__ Al,
    __nv_bfloat16* __restrict__ Bth, __nv_bfloat16* __restrict__ Btl)
{
    __shared__ uint32_t cb_sh[QCH * QSTRIDE];   // 40 KB
    __shared__ float hn_sh[QCH];
    __shared__ int idx_sh[QROWS];

    const int tid = threadIdx.x;
    const int warp = tid >> 5, lane = tid & 31;
    const int g = lane >> 2, t = lane & 3;
    const bool isU = blockIdx.x < 256;
    const int svbase = isU ? blockIdx.x * QROWS : (blockIdx.x - 256) * QROWS;
    const float* Wp = isU ? U : B;

    // A fragments: rows warp*32 + g + {0,8,16,24}; cols t + {0,4,8,12}
    uint32_t ahi[2][2][4], alo[2][2][4];   // [mt][kchunk][slot]
    #pragma unroll
    for (int h = 0; h < 4; ++h) {
        int r = svbase + warp * 32 + g + h * 8;
        int off; float rsv;
        if (isU) { off = (r >> 2) * 64 + (r & 3) * 16;    rsv = rsU[r >> 2]; }
        else     { off = (r >> 8) * 4096 + (r & 255) * 16; rsv = rsB[r >> 8]; }
        const int mt = h >> 1, hl = h & 1;
        #pragma unroll
        for (int kc = 0; kc < 2; ++kc)
            #pragma unroll
            for (int s = 0; s < 2; ++s) {
                float v = Wp[off + t + s * 4 + kc * 8] / rsv;
                split_tf32(v, ahi[mt][kc][s * 2 + hl], alo[mt][kc][s * 2 + hl]);
            }
    }

    float bs[4]; int bi[4];
    #pragma unroll
    for (int q = 0; q < 4; ++q) { bs[q] = -FLT_MAX; bi[q] = 0; }

    for (int ch = 0; ch < K_CB; ch += QCH) {
        __syncthreads();
        {
            const uint4* src = (const uint4*)(g_cbsplit + ch * 32);
            for (int i = tid; i < QCH * 8; i += 256) {
                int cw = i >> 3, q = i & 7;
                *(uint4*)&cb_sh[cw * QSTRIDE + q * 4] = src[i];
            }
            if (tid < QCH) hn_sh[tid] = g_hn[ch + tid];
        }
        __syncthreads();

        #pragma unroll 4
        for (int nt = 0; nt < QCH / 8; ++nt) {
            const int n0 = nt * 8;
            const uint32_t* cwp = &cb_sh[(n0 + g) * QSTRIDE + 2 * t];
            uint2 p00 = *(const uint2*)(cwp);
            uint2 p01 = *(const uint2*)(cwp + 8);
            uint2 p10 = *(const uint2*)(cwp + 16);
            uint2 p11 = *(const uint2*)(cwp + 24);
            uint32_t bh0[2] = {p00.x, p01.x}, bl0[2] = {p00.y, p01.y};
            uint32_t bh1[2] = {p10.x, p11.x}, bl1[2] = {p10.y, p11.y};
            float2 hnp = *(const float2*)&hn_sh[n0 + 2 * t];
            const int base = ch + n0 + 2 * t;
            #pragma unroll
            for (int mt = 0; mt < 2; ++mt) {
                float c[4] = {-hnp.x, -hnp.y, -hnp.x, -hnp.y};
                mma_tf32(c, ahi[mt][0], bh0); mma_tf32(c, ahi[mt][1], bh1);
                mma_tf32(c, ahi[mt][0], bl0); mma_tf32(c, ahi[mt][1], bl1);
                mma_tf32(c, alo[mt][0], bh0); mma_tf32(c, alo[mt][1], bh1);
                const int q0 = mt * 2, q1 = mt * 2 + 1;
                if (c[0] > bs[q0]) { bs[q0] = c[0]; bi[q0] = base; }
                if (c[1] > bs[q0]) { bs[q0] = c[1]; bi[q0] = base + 1; }
                if (c[2] > bs[q1]) { bs[q1] = c[2]; bi[q1] = base; }
                if (c[3] > bs[q1]) { bs[q1] = c[3]; bi[q1] = base + 1; }
            }
        }
    }

    // Reduce argmax across the 4 lanes of each row quad (tie -> smaller idx)
    #pragma unroll
    for (int q = 0; q < 4; ++q) {
        float s = bs[q]; int i0 = bi[q];
        #pragma unroll
        for (int d = 1; d <= 2; d <<= 1) {
            float so = __shfl_xor_sync(0xffffffffu, s, d);
            int   io = __shfl_xor_sync(0xffffffffu, i0, d);
            if (so > s || (so == s && io < i0)) { s = so; i0 = io; }
        }
        if (t == 0)
            idx_sh[warp * 32 + g + (q >> 1) * 16 + (q & 1) * 8] = i0;
    }
    __syncwarp();

    // Dequant write: each lane owns one row of the warp's 32.
    {
        const int rloc = warp * 32 + lane;
        const int w = idx_sh[rloc];
        const int r = svbase + rloc;
        const float* cbr = cb + w * D_SUB;
        if (isU) {
            const int urow = r >> 2;
            const float rsv = rsU[urow];
            const int off = urow * 64 + (r & 3) * 16;
            uint32_t* dh = (uint32_t*)(Ah + off);
            uint32_t* dl = (uint32_t*)(Al + off);
            #pragma unroll
            for (int p = 0; p < 8; ++p) {
                float v0 = cbr[2 * p] * rsv;
                float v1 = cbr[2 * p + 1] * rsv;
                __nv_bfloat16 h0 = __float2bfloat16(v0);
                __nv_bfloat16 h1 = __float2bfloat16(v1);
                __nv_bfloat16 l0 = __float2bfloat16(v0 - __bfloat162float(h0));
                __nv_bfloat16 l1 = __float2bfloat16(v1 - __bfloat162float(h1));
                dh[p] = (uint32_t)__bfloat16_as_ushort(h0) |
                        ((uint32_t)__bfloat16_as_ushort(h1) << 16);
                dl[p] = (uint32_t)__bfloat16_as_ushort(l0) |
                        ((uint32_t)__bfloat16_as_ushort(l1) << 16);
            }
        } else {
            const int brow = r >> 8;
            const float rsv = rsB[brow];
            const int nb = (r & 255) * 16;
            #pragma unroll
            for (int j = 0; j < D_SUB; ++j) {
                float v = cbr[j] * rsv;
                __nv_bfloat16 h = __float2bfloat16(v);
                __nv_bfloat16 l = __float2bfloat16(v - __bfloat162float(h));
                Bth[(nb + j) * 64 + brow] = h;
                Btl[(nb + j) * 64 + brow] = l;
            }
        }
    }
}

// ---------------------------------------------------------------------------
// Split-bf16 GEMM on mma.sync (verified round 3, unchanged):
// C[16384,4096] = (Ah+Al) @ (Bh+Bl)^T
// ---------------------------------------------------------------------------
#define OFF_AH 0
#define OFF_AL 16384
#define OFF_BH 32768
#define OFF_BL 49152
#define GEMM_SMEM (4 * 16384)

__device__ __forceinline__ void load_tile_128x64(
    char* smem, int off, const __nv_bfloat16* __restrict__ src, int tid)
{
    #pragma unroll
    for (int it = 0; it < 4; ++it) {
        int i = tid + it * 256;
        int m = i >> 3, q = i & 7;
        uint32_t b = (uint32_t)(m * 128 + q * 16);
        *(uint4*)(smem + off + SW128(b)) = ((const uint4*)(src + m * 64))[q];
    }
}

__global__ __launch_bounds__(256) void mma_gemm_kernel(
    const __nv_bfloat16* __restrict__ Ah, const __nv_bfloat16* __restrict__ Al,
    const __nv_bfloat16* __restrict__ Bh, const __nv_bfloat16* __restrict__ Bl,
    float* __restrict__ C)
{
    extern __shared__ char smem[];
    const uint32_t sbase = smem_u32(smem);
    const int tid = threadIdx.x;
    const int wid = tid >> 5, lane = tid & 31;
    const int row0 = blockIdx.y * 128;
    const int col0 = blockIdx.x * 128;

    load_tile_128x64(smem, OFF_AH, Ah + (size_t)row0 * R_DIM, tid);
    load_tile_128x64(smem, OFF_AL, Al + (size_t)row0 * R_DIM, tid);
    load_tile_128x64(smem, OFF_BH, Bh + (size_t)col0 * R_DIM, tid);
    load_tile_128x64(smem, OFF_BL, Bl + (size_t)col0 * R_DIM, tid);
    __syncthreads();

    const int warp_m = wid & 3;
    const int warp_n = wid >> 2;
    const int mbase = warp_m * 32;
    const int nbase = warp_n * 64;

    const int a_row = mbase + (lane & 15);
    const int a_kb  = (lane >> 4) * 16;
    const int b_nrow = nbase + (lane & 7) + (lane >> 4) * 8;
    const int b_kb   = ((lane >> 3) & 1) * 16;

    float acc[2][8][4];
    #pragma unroll
    for (int mt = 0; mt < 2; ++mt)
        #pragma unroll
        for (int nt = 0; nt < 8; ++nt)
            #pragma unroll
            for (int q = 0; q < 4; ++q) acc[mt][nt][q] = 0.f;

    #pragma unroll
    for (int pass = 0; pass < 3; ++pass) {
        const uint32_t abase = sbase + (pass == 2 ? OFF_AL : OFF_AH);
        const uint32_t bbase = sbase + (pass == 1 ? OFF_BL : OFF_BH);
        #pragma unroll
        for (int k = 0; k < 4; ++k) {
            uint32_t a[2][4];
            #pragma unroll
            for (int mt = 0; mt < 2; ++mt) {
                uint32_t b = (uint32_t)((a_row + mt * 16) * 128 + k * 32 + a_kb);
                ldmatrix_x4(a[mt], abase + SW128(b));
            }
            uint32_t bf[8][2];
            #pragma unroll
            for (int np = 0; np < 4; ++np) {
                uint32_t b = (uint32_t)((b_nrow + np * 16) * 128 + k * 32 + b_kb);
                uint32_t r[4];
                ldmatrix_x4(r, bbase + SW128(b));
                bf[np * 2][0] = r[0]; bf[np * 2][1] = r[1];
                bf[np * 2 + 1][0] = r[2]; bf[np * 2 + 1][1] = r[3];
            }
            #pragma unroll
            for (int mt = 0; mt < 2; ++mt)
                #pragma unroll
                for (int nt = 0; nt < 8; ++nt)
                    mma_bf16(acc[mt][nt], a[mt], bf[nt]);
        }
    }

    const int g = lane >> 2, t = lane & 3;
    #pragma unroll
    for (int mt = 0; mt < 2; ++mt) {
        float* Cr0 = C + (size_t)(row0 + mbase + mt * 16 + g) * D_DIM + col0 + nbase;
        float* Cr1 = Cr0 + 8 * D_DIM;
        #pragma unroll
        for (int nt = 0; nt < 8; ++nt) {
            *(float2*)(Cr0 + nt * 8 + t * 2) =
                make_float2(acc[mt][nt][0], acc[mt][nt][1]);
            *(float2*)(Cr1 + nt * 8 + t * 2) =
                make_float2(acc[mt][nt][2], acc[mt][nt][3]);
        }
    }
}

// ---------------------------------------------------------------------------
extern "C" void kernel_launch(void* const* d_in, const int* in_sizes, int n_in,
                              void* d_out, int out_size)
{
    (void)in_sizes; (void)n_in; (void)out_size;
    const float* U   = (const float*)d_in[0];
    const float* B   = (const float*)d_in[1];
    const float* rsU = (const float*)d_in[2];
    const float* rsB = (const float*)d_in[3];
    const float* cb  = (const float*)d_in[4];
    float* out = (float*)d_out;

    __nv_bfloat16 *ah, *al, *bh, *bl;
    cudaGetSymbolAddress((void**)&ah, g_Ah);
    cudaGetSymbolAddress((void**)&al, g_Al);
    cudaGetSymbolAddress((void**)&bh, g_Bh);
    cudaGetSymbolAddress((void**)&bl, g_Bl);

    cb_prep_kernel<<<8, 256>>>(cb);
    pq_argmin_kernel<<<320, 256>>>(U, B, rsU, rsB, cb, ah, al, bh, bl);

    cudaFuncSetAttribute(mma_gemm_kernel,
                         cudaFuncAttributeMaxDynamicSharedMemorySize, GEMM_SMEM);
    dim3 grid(D_DIM / 128, K_HOT / 128);
    mma_gemm_kernel<<<grid, 256, GEMM_SMEM>>>(ah, al, bh, bl, out);
}

// round 6
// speedup vs baseline: 2.1741x; 1.0741x over previous
#include <cuda_runtime.h>
#include <cuda_fp16.h>
#include <cstdint>
#include <cfloat>

// Problem constants (fixed shapes for PQHotShared)
#define K_HOT   16384
#define R_DIM   64
#define D_DIM   4096
#define K_CB    2048
#define D_SUB   16

// Scratch (device globals — no allocation allowed)
__device__ __half g_Af[K_HOT * R_DIM];          // A as fp16 (single)
__device__ __half g_Bh[D_DIM * R_DIM];          // B^T hi fp16 [n][k]
__device__ __half g_Bl[D_DIM * R_DIM];          // B^T lo fp16 [n][k]
__device__ uint32_t g_cbsplit[K_CB * 32];       // per cw: [2k]=tf32 hi, [2k+1]=tf32 lo
__device__ float    g_hn[K_CB];                 // 0.5*||cb||^2

#define SW128(b) ((b) ^ (((b) >> 3) & 0x70))

__device__ __forceinline__ uint32_t smem_u32(const void* p) {
    uint32_t a;
    asm("{ .reg .u64 t; cvta.to.shared.u64 t, %1; cvt.u32.u64 %0, t; }"
        : "=r"(a) : "l"(p));
    return a;
}

__device__ __forceinline__ void ldmatrix_x4(uint32_t* r, uint32_t addr) {
    asm volatile("ldmatrix.sync.aligned.m8n8.x4.shared.b16 {%0,%1,%2,%3}, [%4];"
                 : "=r"(r[0]), "=r"(r[1]), "=r"(r[2]), "=r"(r[3]) : "r"(addr));
}

__device__ __forceinline__ void mma_f16(float* c, const uint32_t* a,
                                        const uint32_t* b) {
    asm volatile(
        "mma.sync.aligned.m16n8k16.row.col.f32.f16.f16.f32 "
        "{%0,%1,%2,%3}, {%4,%5,%6,%7}, {%8,%9}, {%0,%1,%2,%3};"
        : "+f"(c[0]), "+f"(c[1]), "+f"(c[2]), "+f"(c[3])
        : "r"(a[0]), "r"(a[1]), "r"(a[2]), "r"(a[3]), "r"(b[0]), "r"(b[1]));
}

__device__ __forceinline__ void mma_tf32(float* c, const uint32_t* a,
                                         const uint32_t* b) {
    asm volatile(
        "mma.sync.aligned.m16n8k8.row.col.f32.tf32.tf32.f32 "
        "{%0,%1,%2,%3}, {%4,%5,%6,%7}, {%8,%9}, {%0,%1,%2,%3};"
        : "+f"(c[0]), "+f"(c[1]), "+f"(c[2]), "+f"(c[3])
        : "r"(a[0]), "r"(a[1]), "r"(a[2]), "r"(a[3]), "r"(b[0]), "r"(b[1]));
}

__device__ __forceinline__ void split_tf32(float v, uint32_t& hi, uint32_t& lo) {
    uint32_t h;
    asm("cvt.rna.tf32.f32 %0, %1;" : "=r"(h) : "f"(v));
    float l = v - __uint_as_float(h);
    uint32_t lw;
    asm("cvt.rna.tf32.f32 %0, %1;" : "=r"(lw) : "f"(l));
    hi = h; lo = lw;
}

// ---------------------------------------------------------------------------
// Codebook prep: tf32 hi/lo split (interleaved) + half squared norms.
// ---------------------------------------------------------------------------
__global__ __launch_bounds__(256) void cb_prep_kernel(const float* __restrict__ cb)
{
    int cw = blockIdx.x * 256 + threadIdx.x;
    if (cw >= K_CB) return;
    float hn = 0.f;
    uint32_t out[32];
    #pragma unroll
    for (int j = 0; j < D_SUB; ++j) {
        float v = cb[cw * D_SUB + j];
        hn = fmaf(v, v, hn);
        split_tf32(v, out[2 * j], out[2 * j + 1]);
    }
    g_hn[cw] = 0.5f * hn;
    uint4* dst = (uint4*)&g_cbsplit[cw * 32];
    #pragma unroll
    for (int q = 0; q < 8; ++q)
        dst[q] = make_uint4(out[4 * q], out[4 * q + 1], out[4 * q + 2], out[4 * q + 3]);
}

// ---------------------------------------------------------------------------
// Fused PQ argmin via split-tf32 mma + dequant to fp16 GEMM operands.
// Block = 256 subvector rows (8 warps x 2 m16-tiles). Blocks [0,256): U rows,
// [256,320): B rows (written transposed).
// ---------------------------------------------------------------------------
#define QROWS 256
#define QCH   256
#define QSTRIDE 40

__global__ __launch_bounds__(256) void pq_argmin_kernel(
    const float* __restrict__ U, const float* __restrict__ B,
    const float* __restrict__ rsU, const float* __restrict__ rsB,
    const float* __restrict__ cb,
    __half* __restrict__ Af,
    __half* __restrict__ Bth, __half* __restrict__ Btl)
{
    __shared__ uint32_t cb_sh[QCH * QSTRIDE];   // 40 KB
    __shared__ float hn_sh[QCH];
    __shared__ int idx_sh[QROWS];

    const int tid = threadIdx.x;
    const int warp = tid >> 5, lane = tid & 31;
    const int g = lane >> 2, t = lane & 3;
    const bool isU = blockIdx.x < 256;
    const int svbase = isU ? blockIdx.x * QROWS : (blockIdx.x - 256) * QROWS;
    const float* Wp = isU ? U : B;

    // A fragments: rows warp*32 + g + {0,8,16,24}; cols t + {0,4,8,12}
    uint32_t ahi[2][2][4], alo[2][2][4];   // [mt][kchunk][slot]
    #pragma unroll
    for (int h = 0; h < 4; ++h) {
        int r = svbase + warp * 32 + g + h * 8;
        int off; float rsv;
        if (isU) { off = (r >> 2) * 64 + (r & 3) * 16;    rsv = rsU[r >> 2]; }
        else     { off = (r >> 8) * 4096 + (r & 255) * 16; rsv = rsB[r >> 8]; }
        const int mt = h >> 1, hl = h & 1;
        #pragma unroll
        for (int kc = 0; kc < 2; ++kc)
            #pragma unroll
            for (int s = 0; s < 2; ++s) {
                float v = Wp[off + t + s * 4 + kc * 8] / rsv;
                split_tf32(v, ahi[mt][kc][s * 2 + hl], alo[mt][kc][s * 2 + hl]);
            }
    }

    float bs[4]; int bi[4];
    #pragma unroll
    for (int q = 0; q < 4; ++q) { bs[q] = -FLT_MAX; bi[q] = 0; }

    for (int ch = 0; ch < K_CB; ch += QCH) {
        __syncthreads();
        {
            const uint4* src = (const uint4*)(g_cbsplit + ch * 32);
            for (int i = tid; i < QCH * 8; i += 256) {
                int cw = i >> 3, q = i & 7;
                *(uint4*)&cb_sh[cw * QSTRIDE + q * 4] = src[i];
            }
            if (tid < QCH) hn_sh[tid] = g_hn[ch + tid];
        }
        __syncthreads();

        #pragma unroll 4
        for (int nt = 0; nt < QCH / 8; ++nt) {
            const int n0 = nt * 8;
            const uint32_t* cwp = &cb_sh[(n0 + g) * QSTRIDE + 2 * t];
            uint2 p00 = *(const uint2*)(cwp);
            uint2 p01 = *(const uint2*)(cwp + 8);
            uint2 p10 = *(const uint2*)(cwp + 16);
            uint2 p11 = *(const uint2*)(cwp + 24);
            uint32_t bh0[2] = {p00.x, p01.x}, bl0[2] = {p00.y, p01.y};
            uint32_t bh1[2] = {p10.x, p11.x}, bl1[2] = {p10.y, p11.y};
            float2 hnp = *(const float2*)&hn_sh[n0 + 2 * t];
            const int base = ch + n0 + 2 * t;
            #pragma unroll
            for (int mt = 0; mt < 2; ++mt) {
                float c[4] = {-hnp.x, -hnp.y, -hnp.x, -hnp.y};
                mma_tf32(c, ahi[mt][0], bh0); mma_tf32(c, ahi[mt][1], bh1);
                mma_tf32(c, ahi[mt][0], bl0); mma_tf32(c, ahi[mt][1], bl1);
                mma_tf32(c, alo[mt][0], bh0); mma_tf32(c, alo[mt][1], bh1);
                const int q0 = mt * 2, q1 = mt * 2 + 1;
                if (c[0] > bs[q0]) { bs[q0] = c[0]; bi[q0] = base; }
                if (c[1] > bs[q0]) { bs[q0] = c[1]; bi[q0] = base + 1; }
                if (c[2] > bs[q1]) { bs[q1] = c[2]; bi[q1] = base; }
                if (c[3] > bs[q1]) { bs[q1] = c[3]; bi[q1] = base + 1; }
            }
        }
    }

    // Reduce argmax across the 4 lanes of each row quad (tie -> smaller idx)
    #pragma unroll
    for (int q = 0; q < 4; ++q) {
        float s = bs[q]; int i0 = bi[q];
        #pragma unroll
        for (int d = 1; d <= 2; d <<= 1) {
            float so = __shfl_xor_sync(0xffffffffu, s, d);
            int   io = __shfl_xor_sync(0xffffffffu, i0, d);
            if (so > s || (so == s && io < i0)) { s = so; i0 = io; }
        }
        if (t == 0)
            idx_sh[warp * 32 + g + (q >> 1) * 16 + (q & 1) * 8] = i0;
    }
    __syncwarp();

    // Dequant write: each lane owns one row of the warp's 32.
    {
        const int rloc = warp * 32 + lane;
        const int w = idx_sh[rloc];
        const int r = svbase + rloc;
        const float* cbr = cb + w * D_SUB;
        if (isU) {
            const int urow = r >> 2;
            const float rsv = rsU[urow];
            const int off = urow * 64 + (r & 3) * 16;
            uint32_t* df = (uint32_t*)(Af + off);
            #pragma unroll
            for (int p = 0; p < 8; ++p) {
                __half h0 = __float2half(cbr[2 * p] * rsv);
                __half h1 = __float2half(cbr[2 * p + 1] * rsv);
                df[p] = (uint32_t)__half_as_ushort(h0) |
                        ((uint32_t)__half_as_ushort(h1) << 16);
            }
        } else {
            const int brow = r >> 8;
            const float rsv = rsB[brow];
            const int nb = (r & 255) * 16;
            #pragma unroll
            for (int j = 0; j < D_SUB; ++j) {
                float v = cbr[j] * rsv;
                __half h = __float2half(v);
                __half l = __float2half(v - __half2float(h));
                Bth[(nb + j) * 64 + brow] = h;
                Btl[(nb + j) * 64 + brow] = l;
            }
        }
    }
}

// ---------------------------------------------------------------------------
// fp16 2-pass GEMM on mma.sync: C[16384,4096] = Af @ (Bh+Bl)^T, fp32 acc.
// A, Bt K-major (64 fp16 = 128 B rows), SW128-swizzled SMEM, conflict-free
// ldmatrix. 128x128 block, 8 warps (4x2), 32x64 per warp. A frags reused
// across both B passes.
// ---------------------------------------------------------------------------
#define OFF_AF 0
#define OFF_BH 16384
#define OFF_BL 32768
#define GEMM_SMEM (3 * 16384)

__device__ __forceinline__ void load_tile_128x64(
    char* smem, int off, const __half* __restrict__ src, int tid)
{
    #pragma unroll
    for (int it = 0; it < 4; ++it) {
        int i = tid + it * 256;
        int m = i >> 3, q = i & 7;
        uint32_t b = (uint32_t)(m * 128 + q * 16);
        *(uint4*)(smem + off + SW128(b)) = ((const uint4*)(src + m * 64))[q];
    }
}

__global__ __launch_bounds__(256, 2) void mma_gemm_kernel(
    const __half* __restrict__ Af,
    const __half* __restrict__ Bh, const __half* __restrict__ Bl,
    float* __restrict__ C)
{
    extern __shared__ char smem[];
    const uint32_t sbase = smem_u32(smem);
    const int tid = threadIdx.x;
    const int wid = tid >> 5, lane = tid & 31;
    const int row0 = blockIdx.y * 128;
    const int col0 = blockIdx.x * 128;

    load_tile_128x64(smem, OFF_AF, Af + (size_t)row0 * R_DIM, tid);
    load_tile_128x64(smem, OFF_BH, Bh + (size_t)col0 * R_DIM, tid);
    load_tile_128x64(smem, OFF_BL, Bl + (size_t)col0 * R_DIM, tid);
    __syncthreads();

    const int warp_m = wid & 3;
    const int warp_n = wid >> 2;
    const int mbase = warp_m * 32;
    const int nbase = warp_n * 64;

    const int a_row = mbase + (lane & 15);
    const int a_kb  = (lane >> 4) * 16;
    const int b_nrow = nbase + (lane & 7) + (lane >> 4) * 8;
    const int b_kb   = ((lane >> 3) & 1) * 16;

    float acc[2][8][4];
    #pragma unroll
    for (int mt = 0; mt < 2; ++mt)
        #pragma unroll
        for (int nt = 0; nt < 8; ++nt)
            #pragma unroll
            for (int q = 0; q < 4; ++q) acc[mt][nt][q] = 0.f;

    #pragma unroll
    for (int k = 0; k < 4; ++k) {
        uint32_t a[2][4];
        #pragma unroll
        for (int mt = 0; mt < 2; ++mt) {
            uint32_t b = (uint32_t)((a_row + mt * 16) * 128 + k * 32 + a_kb);
            ldmatrix_x4(a[mt], sbase + OFF_AF + SW128(b));
        }
        // pass over Bh then Bl, A frags reused (both accumulate into acc)
        #pragma unroll
        for (int pass = 0; pass < 2; ++pass) {
            const uint32_t bbase = sbase + (pass ? OFF_BL : OFF_BH);
            uint32_t bf[8][2];
            #pragma unroll
            for (int np = 0; np < 4; ++np) {
                uint32_t b = (uint32_t)((b_nrow + np * 16) * 128 + k * 32 + b_kb);
                uint32_t r[4];
                ldmatrix_x4(r, bbase + SW128(b));
                bf[np * 2][0] = r[0]; bf[np * 2][1] = r[1];
                bf[np * 2 + 1][0] = r[2]; bf[np * 2 + 1][1] = r[3];
            }
            #pragma unroll
            for (int mt = 0; mt < 2; ++mt)
                #pragma unroll
                for (int nt = 0; nt < 8; ++nt)
                    mma_f16(acc[mt][nt], a[mt], bf[nt]);
        }
    }

    const int g = lane >> 2, t = lane & 3;
    #pragma unroll
    for (int mt = 0; mt < 2; ++mt) {
        float* Cr0 = C + (size_t)(row0 + mbase + mt * 16 + g) * D_DIM + col0 + nbase;
        float* Cr1 = Cr0 + 8 * D_DIM;
        #pragma unroll
        for (int nt = 0; nt < 8; ++nt) {
            *(float2*)(Cr0 + nt * 8 + t * 2) =
                make_float2(acc[mt][nt][0], acc[mt][nt][1]);
            *(float2*)(Cr1 + nt * 8 + t * 2) =
                make_float2(acc[mt][nt][2], acc[mt][nt][3]);
        }
    }
}

// ---------------------------------------------------------------------------
extern "C" void kernel_launch(void* const* d_in, const int* in_sizes, int n_in,
                              void* d_out, int out_size)
{
    (void)in_sizes; (void)n_in; (void)out_size;
    const float* U   = (const float*)d_in[0];
    const float* B   = (const float*)d_in[1];
    const float* rsU = (const float*)d_in[2];
    const float* rsB = (const float*)d_in[3];
    const float* cb  = (const float*)d_in[4];
    float* out = (float*)d_out;

    __half *af, *bh, *bl;
    cudaGetSymbolAddress((void**)&af, g_Af);
    cudaGetSymbolAddress((void**)&bh, g_Bh);
    cudaGetSymbolAddress((void**)&bl, g_Bl);

    cb_prep_kernel<<<8, 256>>>(cb);
    pq_argmin_kernel<<<320, 256>>>(U, B, rsU, rsB, cb, af, bh, bl);

    cudaFuncSetAttribute(mma_gemm_kernel,
                         cudaFuncAttributeMaxDynamicSharedMemorySize, GEMM_SMEM);
    dim3 grid(D_DIM / 128, K_HOT / 128);
    mma_gemm_kernel<<<grid, 256, GEMM_SMEM>>>(af, bh, bl, out);
}

// round 7
// speedup vs baseline: 3.2305x; 1.4859x over previous
#include <cuda_runtime.h>
#include <cuda_fp16.h>
#include <cstdint>
#include <cfloat>

// Problem constants (fixed shapes for PQHotShared)
#define K_HOT   16384
#define R_DIM   64
#define D_DIM   4096
#define K_CB    2048
#define D_SUB   16

// Scratch (device globals — no allocation allowed)
__device__ __half g_Af[K_HOT * R_DIM];          // A as fp16 [m][k]
__device__ __half g_Bf[D_DIM * R_DIM];          // B^T as fp16 [n][k]
// Packed codebook, fp16 hi/lo split. Per cw 16 words:
//   words 0..7 : hi pairs, order [p0,p4,p1,p5,p2,p6,p3,p7] (p_i = dims 2i,2i+1)
//   words 8..15: lo pairs, same order
__device__ uint32_t g_cbpack[K_CB * 16];
__device__ float    g_hn[K_CB];                 // 0.5*||cb||^2

#define SW128(b) ((b) ^ (((b) >> 3) & 0x70))

__device__ __forceinline__ uint32_t smem_u32(const void* p) {
    uint32_t a;
    asm("{ .reg .u64 t; cvta.to.shared.u64 t, %1; cvt.u32.u64 %0, t; }"
        : "=r"(a) : "l"(p));
    return a;
}

__device__ __forceinline__ void ldmatrix_x4(uint32_t* r, uint32_t addr) {
    asm volatile("ldmatrix.sync.aligned.m8n8.x4.shared.b16 {%0,%1,%2,%3}, [%4];"
                 : "=r"(r[0]), "=r"(r[1]), "=r"(r[2]), "=r"(r[3]) : "r"(addr));
}

__device__ __forceinline__ void mma_f16(float* c, const uint32_t* a,
                                        const uint32_t* b) {
    asm volatile(
        "mma.sync.aligned.m16n8k16.row.col.f32.f16.f16.f32 "
        "{%0,%1,%2,%3}, {%4,%5,%6,%7}, {%8,%9}, {%0,%1,%2,%3};"
        : "+f"(c[0]), "+f"(c[1]), "+f"(c[2]), "+f"(c[3])
        : "r"(a[0]), "r"(a[1]), "r"(a[2]), "r"(a[3]), "r"(b[0]), "r"(b[1]));
}

__device__ __forceinline__ uint32_t pack_h2(float a, float b) {
    __half2 h = __floats2half2_rn(a, b);   // a -> low half (even k)
    return *(uint32_t*)&h;
}

// ---------------------------------------------------------------------------
// Codebook prep: fp16 hi/lo split, packed for direct mma B-fragment loads,
// plus half squared norms (fp32).
// ---------------------------------------------------------------------------
__global__ __launch_bounds__(256) void cb_prep_kernel(const float* __restrict__ cb)
{
    int cw = blockIdx.x * 256 + threadIdx.x;
    if (cw >= K_CB) return;
    float v[D_SUB];
    float hn = 0.f;
    #pragma unroll
    for (int j = 0; j < D_SUB; ++j) {
        v[j] = cb[cw * D_SUB + j];
        hn = fmaf(v[j], v[j], hn);
    }
    g_hn[cw] = 0.5f * hn;

    float hi[D_SUB], lo[D_SUB];
    #pragma unroll
    for (int j = 0; j < D_SUB; ++j) {
        float h = __half2float(__float2half_rn(v[j]));
        hi[j] = h;
        lo[j] = v[j] - h;
    }
    uint32_t w[16];
    #pragma unroll
    for (int i = 0; i < 4; ++i) {
        int p0 = i, p1 = i + 4;
        w[2 * i]     = pack_h2(hi[2 * p0], hi[2 * p0 + 1]);
        w[2 * i + 1] = pack_h2(hi[2 * p1], hi[2 * p1 + 1]);
        w[8 + 2 * i]     = pack_h2(lo[2 * p0], lo[2 * p0 + 1]);
        w[8 + 2 * i + 1] = pack_h2(lo[2 * p1], lo[2 * p1 + 1]);
    }
    uint4* dst = (uint4*)&g_cbpack[cw * 16];
    #pragma unroll
    for (int q = 0; q < 4; ++q)
        dst[q] = make_uint4(w[4 * q], w[4 * q + 1], w[4 * q + 2], w[4 * q + 3]);
}

// ---------------------------------------------------------------------------
// Fused PQ argmin via fp16-split m16n8k16 mma + dequant to fp16 GEMM operands.
// score = g.cb - hn ~= gh.ch + gh.cl + gl.ch - hn  (dropped gl.cl ~ 2^-22).
// Block = 256 subvector rows. Blocks [0,256): U rows; [256,320): B rows
// (written transposed).
// ---------------------------------------------------------------------------
#define QROWS 256
#define QCH   512
#define QST   24          // words per codeword row in smem (conflict-free)

__global__ __launch_bounds__(256) void pq_argmin_kernel(
    const float* __restrict__ U, const float* __restrict__ B,
    const float* __restrict__ rsU, const float* __restrict__ rsB,
    const float* __restrict__ cb,
    __half* __restrict__ Af, __half* __restrict__ Btf)
{
    __shared__ uint32_t cb_sh[QCH * QST];       // 48 KB
    __shared__ float hn_sh[QCH];                // 2 KB
    __shared__ int idx_sh[QROWS];

    const int tid = threadIdx.x;
    const int warp = tid >> 5, lane = tid & 31;
    const int g = lane >> 2, t = lane & 3;
    const bool isU = blockIdx.x < 256;
    const int svbase = isU ? blockIdx.x * QROWS : (blockIdx.x - 256) * QROWS;
    const float* Wp = isU ? U : B;

    // A fragments (fp16 hi/lo). Regs: [mt][{a0,a1,a2,a3}] with
    // a0=(row g, kp t), a1=(row g+8, kp t), a2=(row g, kp t+4), a3=(row g+8, kp t+4)
    uint32_t ahi[2][4], alo[2][4];
    #pragma unroll
    for (int h = 0; h < 4; ++h) {
        const int mt = h >> 1, rh = h & 1;
        int r = svbase + warp * 32 + mt * 16 + rh * 8 + g;
        int off; float rsv;
        if (isU) { off = (r >> 2) * 64 + (r & 3) * 16;     rsv = rsU[r >> 2]; }
        else     { off = (r >> 8) * 4096 + (r & 255) * 16; rsv = rsB[r >> 8]; }
        float v0 = Wp[off + 2 * t]     / rsv;
        float v1 = Wp[off + 2 * t + 1] / rsv;
        float v2 = Wp[off + 8 + 2 * t]     / rsv;
        float v3 = Wp[off + 8 + 2 * t + 1] / rsv;
        float h0 = __half2float(__float2half_rn(v0));
        float h1 = __half2float(__float2half_rn(v1));
        float h2 = __half2float(__float2half_rn(v2));
        float h3 = __half2float(__float2half_rn(v3));
        ahi[mt][rh]     = pack_h2(h0, h1);
        ahi[mt][2 + rh] = pack_h2(h2, h3);
        alo[mt][rh]     = pack_h2(v0 - h0, v1 - h1);
        alo[mt][2 + rh] = pack_h2(v2 - h2, v3 - h3);
    }

    float bs[4]; int bi[4];
    #pragma unroll
    for (int q = 0; q < 4; ++q) { bs[q] = -FLT_MAX; bi[q] = 0; }

    for (int ch = 0; ch < K_CB; ch += QCH) {
        __syncthreads();
        {
            const uint4* src = (const uint4*)(g_cbpack + ch * 16);
            for (int i = tid; i < QCH * 4; i += 256) {
                int cw = i >> 2, q = i & 3;
                *(uint4*)&cb_sh[cw * QST + q * 4] = src[i];
            }
            for (int i = tid; i < QCH; i += 256)
                hn_sh[i] = g_hn[ch + i];
        }
        __syncthreads();

        #pragma unroll 4
        for (int nt = 0; nt < QCH / 8; ++nt) {
            const int n0 = nt * 8;
            const uint32_t* cwp = &cb_sh[(n0 + g) * QST];
            uint2 bhp = *(const uint2*)(cwp + 2 * t);        // (h_t, h_{t+4})
            uint2 blp = *(const uint2*)(cwp + 8 + 2 * t);    // (l_t, l_{t+4})
            uint32_t bh[2] = {bhp.x, bhp.y};
            uint32_t bl[2] = {blp.x, blp.y};
            float2 hnp = *(const float2*)&hn_sh[n0 + 2 * t];
            const int base = ch + n0 + 2 * t;
            #pragma unroll
            for (int mt = 0; mt < 2; ++mt) {
                float c[4] = {-hnp.x, -hnp.y, -hnp.x, -hnp.y};
                mma_f16(c, ahi[mt], bh);
                mma_f16(c, ahi[mt], bl);
                mma_f16(c, alo[mt], bh);
                const int q0 = mt * 2, q1 = mt * 2 + 1;
                if (c[0] > bs[q0]) { bs[q0] = c[0]; bi[q0] = base; }
                if (c[1] > bs[q0]) { bs[q0] = c[1]; bi[q0] = base + 1; }
                if (c[2] > bs[q1]) { bs[q1] = c[2]; bi[q1] = base; }
                if (c[3] > bs[q1]) { bs[q1] = c[3]; bi[q1] = base + 1; }
            }
        }
    }

    // Reduce argmax across the 4 t-lanes of each row quad (tie -> smaller idx)
    #pragma unroll
    for (int q = 0; q < 4; ++q) {
        float s = bs[q]; int i0 = bi[q];
        #pragma unroll
        for (int d = 1; d <= 2; d <<= 1) {
            float so = __shfl_xor_sync(0xffffffffu, s, d);
            int   io = __shfl_xor_sync(0xffffffffu, i0, d);
            if (so > s || (so == s && io < i0)) { s = so; i0 = io; }
        }
        if (t == 0)
            idx_sh[warp * 32 + (q >> 1) * 16 + (q & 1) * 8 + g] = i0;
    }
    __syncwarp();

    // Dequant write: each lane owns one row of the warp's 32.
    {
        const int rloc = warp * 32 + lane;
        const int w = idx_sh[rloc];
        const int r = svbase + rloc;
        const float* cbr = cb + w * D_SUB;
        if (isU) {
            const int urow = r >> 2;
            const float rsv = rsU[urow];
            const int off = urow * 64 + (r & 3) * 16;
            uint32_t* df = (uint32_t*)(Af + off);
            #pragma unroll
            for (int p = 0; p < 8; ++p)
                df[p] = pack_h2(cbr[2 * p] * rsv, cbr[2 * p + 1] * rsv);
        } else {
            const int brow = r >> 8;
            const float rsv = rsB[brow];
            const int nb = (r & 255) * 16;
            #pragma unroll
            for (int j = 0; j < D_SUB; ++j)
                Btf[(nb + j) * 64 + brow] = __float2half_rn(cbr[j] * rsv);
        }
    }
}

// ---------------------------------------------------------------------------
// fp16 single-pass GEMM on mma.sync: C[16384,4096] = Af @ Bf^T, fp32 acc.
// A, Bt K-major (64 fp16 = 128 B rows), SW128-swizzled SMEM, conflict-free
// ldmatrix. 128x128 block, 8 warps (4x2), 32x64 per warp.
// ---------------------------------------------------------------------------
#define OFF_AF 0
#define OFF_BF 16384
#define GEMM_SMEM (2 * 16384)

__device__ __forceinline__ void load_tile_128x64(
    char* smem, int off, const __half* __restrict__ src, int tid)
{
    #pragma unroll
    for (int it = 0; it < 4; ++it) {
        int i = tid + it * 256;
        int m = i >> 3, q = i & 7;
        uint32_t b = (uint32_t)(m * 128 + q * 16);
        *(uint4*)(smem + off + SW128(b)) = ((const uint4*)(src + m * 64))[q];
    }
}

__global__ __launch_bounds__(256, 2) void mma_gemm_kernel(
    const __half* __restrict__ Af, const __half* __restrict__ Bf,
    float* __restrict__ C)
{
    extern __shared__ char smem[];
    const uint32_t sbase = smem_u32(smem);
    const int tid = threadIdx.x;
    const int wid = tid >> 5, lane = tid & 31;
    const int row0 = blockIdx.y * 128;
    const int col0 = blockIdx.x * 128;

    load_tile_128x64(smem, OFF_AF, Af + (size_t)row0 * R_DIM, tid);
    load_tile_128x64(smem, OFF_BF, Bf + (size_t)col0 * R_DIM, tid);
    __syncthreads();

    const int warp_m = wid & 3;
    const int warp_n = wid >> 2;
    const int mbase = warp_m * 32;
    const int nbase = warp_n * 64;

    const int a_row = mbase + (lane & 15);
    const int a_kb  = (lane >> 4) * 16;
    const int b_nrow = nbase + (lane & 7) + (lane >> 4) * 8;
    const int b_kb   = ((lane >> 3) & 1) * 16;

    float acc[2][8][4];
    #pragma unroll
    for (int mt = 0; mt < 2; ++mt)
        #pragma unroll
        for (int nt = 0; nt < 8; ++nt)
            #pragma unroll
            for (int q = 0; q < 4; ++q) acc[mt][nt][q] = 0.f;

    #pragma unroll
    for (int k = 0; k < 4; ++k) {
        uint32_t a[2][4];
        #pragma unroll
        for (int mt = 0; mt < 2; ++mt) {
            uint32_t b = (uint32_t)((a_row + mt * 16) * 128 + k * 32 + a_kb);
            ldmatrix_x4(a[mt], sbase + OFF_AF + SW128(b));
        }
        uint32_t bf[8][2];
        #pragma unroll
        for (int np = 0; np < 4; ++np) {
            uint32_t b = (uint32_t)((b_nrow + np * 16) * 128 + k * 32 + b_kb);
            uint32_t r[4];
            ldmatrix_x4(r, sbase + OFF_BF + SW128(b));
            bf[np * 2][0] = r[0]; bf[np * 2][1] = r[1];
            bf[np * 2 + 1][0] = r[2]; bf[np * 2 + 1][1] = r[3];
        }
        #pragma unroll
        for (int mt = 0; mt < 2; ++mt)
            #pragma unroll
            for (int nt = 0; nt < 8; ++nt)
                mma_f16(acc[mt][nt], a[mt], bf[nt]);
    }

    const int g = lane >> 2, t = lane & 3;
    #pragma unroll
    for (int mt = 0; mt < 2; ++mt) {
        float* Cr0 = C + (size_t)(row0 + mbase + mt * 16 + g) * D_DIM + col0 + nbase;
        float* Cr1 = Cr0 + 8 * D_DIM;
        #pragma unroll
        for (int nt = 0; nt < 8; ++nt) {
            *(float2*)(Cr0 + nt * 8 + t * 2) =
                make_float2(acc[mt][nt][0], acc[mt][nt][1]);
            *(float2*)(Cr1 + nt * 8 + t * 2) =
                make_float2(acc[mt][nt][2], acc[mt][nt][3]);
        }
    }
}

// ---------------------------------------------------------------------------
extern "C" void kernel_launch(void* const* d_in, const int* in_sizes, int n_in,
                              void* d_out, int out_size)
{
    (void)in_sizes; (void)n_in; (void)out_size;
    const float* U   = (const float*)d_in[0];
    const float* B   = (const float*)d_in[1];
    const float* rsU = (const float*)d_in[2];
    const float* rsB = (const float*)d_in[3];
    const float* cb  = (const float*)d_in[4];
    float* out = (float*)d_out;

    __half *af, *bf;
    cudaGetSymbolAddress((void**)&af, g_Af);
    cudaGetSymbolAddress((void**)&bf, g_Bf);

    cb_prep_kernel<<<8, 256>>>(cb);
    pq_argmin_kernel<<<320, 256>>>(U, B, rsU, rsB, cb, af, bf);

    cudaFuncSetAttribute(mma_gemm_kernel,
                         cudaFuncAttributeMaxDynamicSharedMemorySize, GEMM_SMEM);
    dim3 grid(D_DIM / 128, K_HOT / 128);
    mma_gemm_kernel<<<grid, 256, GEMM_SMEM>>>(af, bf, out);
}